// round 10
// baseline (speedup 1.0000x reference)
#include <cuda_runtime.h>
#include <math.h>

#define NLM 25
#define NPATH 65
#define PENT_STRIDE 320
#define SEG_STRIDE 9
#define RSEG_STRIDE 128
#define PI_F 3.14159265358979323846f
#define CUTOFF_F 5.0f
#define MAXN 10240
#define TBLOCKS 62   // ceil(25^3 / 256)

typedef unsigned long long ull;

// ---------------- scratch (static __device__, no allocations) ----------------
__device__ float  g_y0[MAXN * NLM * 16];
__device__ float  g_y1[MAXN * 2 * NLM * 64];
__device__ float  g_y2[MAXN * 2 * NLM * 64];
__device__ float  g_CG[NLM * NLM * NLM];
__device__ int2   g_pent[NPATH * PENT_STRIDE];    // (a*256 | (b*256)<<16, cg)  [64-f rows]
__device__ int2   g_pent2[NPATH * PENT_STRIDE];   // (a*512 | (b*512)<<16, cg)  [128-f parity-major rows]
__device__ int    g_pseg[NPATH * SEG_STRIDE];     // c | cnt<<8
__device__ int    g_psegcnt[NPATH];
__device__ int    g_pathS[NPATH];
__device__ int2   g_rseg[4 * RSEG_STRIDE];        // x: off | cnt<<20 ; y: c | s<<5 | path<<6
__device__ int    g_rsegcnt[4];

__constant__ int c_deg[NLM] = {0,1,1,1,2,2,2,2,2,3,3,3,3,3,3,3,4,4,4,4,4,4,4,4,4};

// ---------------- packed f32x2 helpers (operands stay as b64 pairs) ----------------
__device__ __forceinline__ ull pmul2(ull a, ull b) {
    ull d; asm("mul.rn.f32x2 %0, %1, %2;" : "=l"(d) : "l"(a), "l"(b)); return d;
}
__device__ __forceinline__ void pfma2(ull& t, ull a, ull b) {
    asm("fma.rn.f32x2 %0, %1, %2, %0;" : "+l"(t) : "l"(a), "l"(b));
}
__device__ __forceinline__ ull pfma3(ull a, ull b, ull c) {
    ull d; asm("fma.rn.f32x2 %0, %1, %2, %3;" : "=l"(d) : "l"(a), "l"(b), "l"(c)); return d;
}
__device__ __forceinline__ ull padd2(ull a, ull b) {
    ull d; asm("add.rn.f32x2 %0, %1, %2;" : "=l"(d) : "l"(a), "l"(b)); return d;
}
__device__ __forceinline__ ull bcast2(float v) {
    ull d; asm("mov.b64 %0, {%1, %1};" : "=l"(d) : "f"(v)); return d;
}
__device__ __forceinline__ float2 up2(ull v) {
    float2 r; asm("mov.b64 {%0, %1}, %2;" : "=f"(r.x), "=f"(r.y) : "l"(v)); return r;
}

// ---------------- CG construction (exact, fp64, every launch) ----------------
__device__ __forceinline__ double dfact(int n) {
    const double f[16] = {1.0,1.0,2.0,6.0,24.0,120.0,720.0,5040.0,40320.0,
                          362880.0,3628800.0,39916800.0,479001600.0,
                          6227020800.0,87178291200.0,1307674368000.0};
    return f[n];
}

__device__ double cg_complex(int l1,int m1,int l2,int m2,int l3,int m3) {
    if (m1 + m2 != m3 || l3 < abs(l1 - l2) || l3 > l1 + l2) return 0.0;
    double P = dfact(l1+l2-l3) * dfact(l1-l2+l3) * dfact(-l1+l2+l3) / dfact(l1+l2+l3+1)
             * dfact(l1+m1) * dfact(l1-m1) * dfact(l2+m2) * dfact(l2-m2)
             * dfact(l3+m3) * dfact(l3-m3);
    double sp = sqrt(P);
    int kmin = max(0, max(l2 - l3 - m1, l1 - l3 + m2));
    int kmax = min(l1 + l2 - l3, min(l1 - m1, l2 + m2));
    double s = 0.0;
    for (int k = kmin; k <= kmax; k++) {
        double D = dfact(k) * dfact(l1+l2-l3-k) * dfact(l1-m1-k) * dfact(l2+m2-k)
                 * dfact(l3-l2+m1+k) * dfact(l3-l1-m2+k);
        s += ((k & 1) ? -1.0 : 1.0) * sp / D;
    }
    return sqrt(2.0 * l3 + 1.0) * s;
}

__device__ __forceinline__ int u_row(int l, int m, int* col, double* re, double* im) {
    int off = l * l + l;
    const double is2 = 0.7071067811865476;
    if (m == 0) { col[0] = off; re[0] = 1.0; im[0] = 0.0; return 1; }
    if (m > 0) {
        double sgn = (m & 1) ? -1.0 : 1.0;
        col[0] = off + m; re[0] = sgn * is2; im[0] = 0.0;
        col[1] = off - m; re[1] = is2;       im[1] = 0.0;
        return 2;
    }
    int mm = -m;
    double sgn = (mm & 1) ? -1.0 : 1.0;
    col[0] = off - mm; re[0] = 0.0; im[0] = is2;
    col[1] = off + mm; re[1] = 0.0; im[1] = -sgn * is2;
    return 2;
}

__global__ void k_init_T(int tot4) {
    if (blockIdx.x >= TBLOCKS) {
        int t = (blockIdx.x - TBLOCKS) * blockDim.x + threadIdx.x;
        if (t < tot4) ((float4*)g_y0)[t] = make_float4(0.f, 0.f, 0.f, 0.f);
        return;
    }
    int t = blockIdx.x * blockDim.x + threadIdx.x;
    if (t >= NLM * NLM * NLM) return;
    int i = t / (NLM * NLM), j = (t / NLM) % NLM, k = t % NLM;
    int li = c_deg[i], mi = i - li * li - li;
    int lj = c_deg[j], mj = j - lj * lj - lj;
    int lk = c_deg[k], mk = k - lk * lk - lk;

    int ca[2]; double are[2], aim[2]; int na = u_row(li, mi, ca, are, aim);
    int cb[2]; double bre[2], bim[2]; int nb = u_row(lj, mj, cb, bre, bim);
    int cc[2]; double kre[2], kim[2]; int nc = u_row(lk, mk, cc, kre, kim);

    double tre = 0.0, tim = 0.0;
    for (int aa = 0; aa < na; aa++) {
        for (int bb = 0; bb < nb; bb++) {
            double wre = are[aa] * bre[bb] - aim[aa] * bim[bb];
            double wim = are[aa] * bim[bb] + aim[aa] * bre[bb];
            for (int ci = 0; ci < nc; ci++) {
                int a = ca[aa], b = cb[bb], c = cc[ci];
                double cg = cg_complex(li, a - li*li - li, lj, b - lj*lj - lj,
                                       lk, c - lk*lk - lk);
                if (cg == 0.0) continue;
                double ur3 = kre[ci], ui3 = -kim[ci];
                tre += (wre * ur3 - wim * ui3) * cg;
                tim += (wre * ui3 + wim * ur3) * cg;
            }
        }
    }
    double v = tre + tim;
    g_CG[t] = (fabs(v) < 1e-12) ? 0.0f : (float)v;
}

// single block: 32 warps compact paths, thread 0 schedules classes + sorts by c
__global__ void __launch_bounds__(1024) k_init_ents_sched() {
    int lane = threadIdx.x & 31;
    int w = threadIdx.x >> 5;
    for (int p = w; p < NPATH; p += 32) {
        int l1 = 0, l2 = 0, l3 = 0, acc = 0;
        bool found = false;
        for (int a1 = 0; a1 <= 4; a1++)
            for (int a2 = 0; a2 <= 4; a2++) {
                int lo = abs(a1 - a2), hi = min(4, a1 + a2), cnt = hi - lo + 1;
                if (!found) {
                    if (p < acc + cnt) { l1 = a1; l2 = a2; l3 = lo + (p - acc); found = true; }
                    else acc += cnt;
                }
            }
        if (lane == 0) g_pathS[p] = (l1 + l2 + l3) & 1;

        int na = 2 * l1 + 1, nb = 2 * l2 + 1, npair = na * nb;
        int a0 = l1 * l1, b0 = l2 * l2;
        int eb = p * PENT_STRIDE;
        int ne = 0, ns = 0;
        for (int c = l3 * l3; c < (l3 + 1) * (l3 + 1); c++) {
            int segstart = ne;
            for (int base = 0; base < npair; base += 32) {
                int q = base + lane;
                float v = 0.0f; int a = 0, b = 0;
                if (q < npair) {
                    a = a0 + q / nb; b = b0 + q % nb;
                    v = g_CG[(a * NLM + b) * NLM + c];
                }
                unsigned mask = __ballot_sync(0xffffffffu, v != 0.0f);
                if (v != 0.0f) {
                    int pos = ne + __popc(mask & ((1u << lane) - 1u));
                    g_pent[eb + pos]  = make_int2((a * 256) | ((b * 256) << 16), __float_as_int(v));
                    g_pent2[eb + pos] = make_int2((a * 512) | ((b * 512) << 16), __float_as_int(v));
                }
                ne += __popc(mask);
            }
            int cn = ne - segstart;
            int pad = (4 - (cn & 3)) & 3;
            if (cn > 0) {
                if (lane < pad) {
                    g_pent[eb + ne + lane]  = make_int2(0, 0);
                    g_pent2[eb + ne + lane] = make_int2(0, 0);
                }
                ne += pad; cn += pad;
                if (lane == 0) g_pseg[p * SEG_STRIDE + ns] = c | (cn << 8);
                ns++;
            }
        }
        if (lane == 0) g_psegcnt[p] = ns;
    }
    __syncthreads();
    if (threadIdx.x != 0) return;

    int wsum[NLM];
    for (int c = 0; c < NLM; c++) wsum[c] = 0;
    for (int p = 0; p < NPATH; p++) {
        int ns = g_psegcnt[p];
        for (int sg = 0; sg < ns; sg++) {
            int m = g_pseg[p * SEG_STRIDE + sg];
            wsum[m & 255] += (m >> 8) + 8;
        }
    }
    int csel[NLM]; bool used[NLM]; int load[4] = {0, 0, 0, 0};
    for (int c = 0; c < NLM; c++) used[c] = false;
    for (int it = 0; it < NLM; it++) {
        int best = -1, bw = -1;
        for (int c = 0; c < NLM; c++)
            if (!used[c] && wsum[c] > bw) { bw = wsum[c]; best = c; }
        int kmin = 0;
        for (int k = 1; k < 4; k++) if (load[k] < load[kmin]) kmin = k;
        csel[best] = kmin; load[kmin] += bw; used[best] = true;
    }
    int cnt4[4] = {0, 0, 0, 0};
    for (int p = 0; p < NPATH; p++) {
        int off = p * PENT_STRIDE;
        int ns = g_psegcnt[p];
        int s = g_pathS[p];
        for (int sg = 0; sg < ns; sg++) {
            int m = g_pseg[p * SEG_STRIDE + sg];
            int c = m & 255, cn = m >> 8;
            int cls = csel[c];
            g_rseg[cls * RSEG_STRIDE + cnt4[cls]] =
                make_int2(off | (cn << 20), c | (s << 5) | (p << 6));
            cnt4[cls]++;
            off += cn;
        }
    }
    // sort each class list by c (same-c segments contiguous -> register accumulation)
    for (int k = 0; k < 4; k++) {
        int nn = cnt4[k];
        int2* L = g_rseg + k * RSEG_STRIDE;
        for (int i2 = 1; i2 < nn; i2++) {
            int2 key = L[i2];
            int kc = key.y & 31;
            int j2 = i2 - 1;
            while (j2 >= 0 && (L[j2].y & 31) > kc) { L[j2 + 1] = L[j2]; j2--; }
            L[j2 + 1] = key;
        }
        g_rsegcnt[k] = nn;
    }
}

// ---------------- edge kernel ----------------
__global__ void k_edge(const int* __restrict__ nbr, const float* __restrict__ disp,
                       const int* __restrict__ Z, const float* __restrict__ Wsp,
                       const float* __restrict__ normp, int E) {
    int t = blockIdx.x * blockDim.x + threadIdx.x;
    int e = t >> 4, lane = t & 15;
    bool valid = (e < E);
    int i = 0, j = 0;
    float dx = 0.f, dy = 0.f, dz = 1.f;
    if (valid) {
        i = nbr[2 * e]; j = nbr[2 * e + 1];
        dx = disp[3 * e]; dy = disp[3 * e + 1]; dz = disp[3 * e + 2];
    }
    float r = sqrtf(dx * dx + dy * dy + dz * dz + 1e-12f);
    float inv = 1.0f / r;
    float x = dx * inv, y = dy * inv, z = dz * inv;
    bool ok = valid && (r < CUTOFF_F);
    float fcut = 0.5f * (cosf(PI_F * fminf(r * (1.0f / CUTOFF_F), 1.0f)) + 1.0f);

    int Zj = valid ? Z[j] : 0;
    const float gamma = 10.24f;
    float d = r - (float)lane * (CUTOFF_F / 15.0f);
    float rbf = expf(-gamma * d * d);

    const float* W = Wsp + Zj * 256 + lane;
    float gsum = 0.0f;
#pragma unroll
    for (int k = 0; k < 16; k++) {
        float rb = __shfl_sync(0xffffffffu, rbf, k, 16);
        gsum = fmaf(rb, W[k * 16], gsum);
    }
    if (!ok) return;
    float g = gsum * fcut / normp[0];

    float x2 = x * x, y2 = y * y, z2 = z * z;
    float Y[NLM];
    Y[0]  = 0.5f * sqrtf(1.0f / PI_F);
    Y[1]  = sqrtf(3.0f / (4.0f * PI_F)) * y;
    Y[2]  = sqrtf(3.0f / (4.0f * PI_F)) * z;
    Y[3]  = sqrtf(3.0f / (4.0f * PI_F)) * x;
    Y[4]  = 0.5f * sqrtf(15.0f / PI_F) * x * y;
    Y[5]  = 0.5f * sqrtf(15.0f / PI_F) * y * z;
    Y[6]  = 0.25f * sqrtf(5.0f / PI_F) * (3.0f * z2 - 1.0f);
    Y[7]  = 0.5f * sqrtf(15.0f / PI_F) * x * z;
    Y[8]  = 0.25f * sqrtf(15.0f / PI_F) * (x2 - y2);
    Y[9]  = 0.25f * sqrtf(35.0f / (2.0f * PI_F)) * y * (3.0f * x2 - y2);
    Y[10] = 0.5f * sqrtf(105.0f / PI_F) * x * y * z;
    Y[11] = 0.25f * sqrtf(21.0f / (2.0f * PI_F)) * y * (5.0f * z2 - 1.0f);
    Y[12] = 0.25f * sqrtf(7.0f / PI_F) * z * (5.0f * z2 - 3.0f);
    Y[13] = 0.25f * sqrtf(21.0f / (2.0f * PI_F)) * x * (5.0f * z2 - 1.0f);
    Y[14] = 0.25f * sqrtf(105.0f / PI_F) * z * (x2 - y2);
    Y[15] = 0.25f * sqrtf(35.0f / (2.0f * PI_F)) * x * (x2 - 3.0f * y2);
    Y[16] = 0.75f * sqrtf(35.0f / PI_F) * x * y * (x2 - y2);
    Y[17] = 0.75f * sqrtf(35.0f / (2.0f * PI_F)) * y * z * (3.0f * x2 - y2);
    Y[18] = 0.75f * sqrtf(5.0f / PI_F) * x * y * (7.0f * z2 - 1.0f);
    Y[19] = 0.75f * sqrtf(5.0f / (2.0f * PI_F)) * y * z * (7.0f * z2 - 3.0f);
    Y[20] = (3.0f / 16.0f) * sqrtf(1.0f / PI_F) * (35.0f * z2 * z2 - 30.0f * z2 + 3.0f);
    Y[21] = 0.75f * sqrtf(5.0f / (2.0f * PI_F)) * x * z * (7.0f * z2 - 3.0f);
    Y[22] = (3.0f / 8.0f) * sqrtf(5.0f / PI_F) * (x2 - y2) * (7.0f * z2 - 1.0f);
    Y[23] = 0.75f * sqrtf(35.0f / (2.0f * PI_F)) * x * z * (x2 - 3.0f * y2);
    Y[24] = (3.0f / 16.0f) * sqrtf(35.0f / PI_F) * (x2 * x2 - 6.0f * x2 * y2 + y2 * y2);

    float* dst = g_y0 + (size_t)i * (NLM * 16) + lane;
#pragma unroll
    for (int lm = 0; lm < NLM; lm++)
        atomicAdd(dst + lm * 16, Y[lm] * g);
}

// ---- TP layer 0: dense role-split; product = 4 class-warps, dual-half (even/odd
//      entries), 4 features/thread, packed f32x2, register c-accum, direct stores ----
__global__ void __launch_bounds__(128) k_tp0(const float* __restrict__ W1,
                                             const float* __restrict__ W2,
                                             const float* __restrict__ wp) {
    __shared__ __align__(16) float sa[NLM * 64];
    __shared__ __align__(16) float sb[NLM * 64];
    int n = blockIdx.x;
    int tid = threadIdx.x;
    int g = tid & 63;
    int drole = tid >> 6;

    const float* yin = g_y0 + (size_t)n * (NLM * 16);
    const float* Wm = drole ? W2 : W1;
    float* dst = drole ? sb : sa;

    for (int d = 0; d < 5; d++) {
        float w[16];
        const float* Wb = Wm + (d * 16) * 64 + g;
#pragma unroll
        for (int f = 0; f < 16; f++) w[f] = Wb[f * 64];
        for (int lm = d * d; lm < (d + 1) * (d + 1); lm++) {
            const float4* s4 = (const float4*)(yin + lm * 16);
            float a0 = 0.f, a1 = 0.f, a2 = 0.f, a3 = 0.f;
#pragma unroll
            for (int k = 0; k < 4; k++) {
                float4 v = s4[k];
                a0 = fmaf(v.x, w[4*k+0], a0);
                a1 = fmaf(v.y, w[4*k+1], a1);
                a2 = fmaf(v.z, w[4*k+2], a2);
                a3 = fmaf(v.w, w[4*k+3], a3);
            }
            dst[lm * 64 + g] = (a0 + a1) + (a2 + a3);
        }
    }
    __syncthreads();

    int q = tid & 15;
    int half = (tid >> 4) & 1;
    int role = tid >> 5;
    const char* sab = (const char*)sa + 16 * q;
    const char* sbb = (const char*)sb + 16 * q;
    float* yo = g_y1 + (size_t)n * (2 * NLM * 64);
    int nseg = g_rsegcnt[role];
    const int2* rs = g_rseg + role * RSEG_STRIDE;
    ull acc0a = 0, acc0b = 0, acc1a = 0, acc1b = 0;   // packed feature-pair accumulators
    int curc = -1;
    for (int si = 0; si < nseg; si++) {
        int2 m = rs[si];
        int off = m.x & 0xFFFFF;
        int cnt = ((unsigned)m.x) >> 20;
        int c = m.y & 31, s = (m.y >> 5) & 1, p = m.y >> 6;
        if (c != curc) {
            if (curc >= 0) {
                float2 e0 = up2(acc0a), e1 = up2(acc0b), o0 = up2(acc1a), o1 = up2(acc1b);
                e0.x += __shfl_down_sync(0xffffffffu, e0.x, 16);
                e0.y += __shfl_down_sync(0xffffffffu, e0.y, 16);
                e1.x += __shfl_down_sync(0xffffffffu, e1.x, 16);
                e1.y += __shfl_down_sync(0xffffffffu, e1.y, 16);
                o0.x += __shfl_down_sync(0xffffffffu, o0.x, 16);
                o0.y += __shfl_down_sync(0xffffffffu, o0.y, 16);
                o1.x += __shfl_down_sync(0xffffffffu, o1.x, 16);
                o1.y += __shfl_down_sync(0xffffffffu, o1.y, 16);
                if (half == 0) {
                    *(float4*)&yo[curc * 64 + 4 * q] = make_float4(e0.x, e0.y, e1.x, e1.y);
                    *(float4*)&yo[(NLM + curc) * 64 + 4 * q] = make_float4(o0.x, o0.y, o1.x, o1.y);
                }
            }
            acc0a = acc0b = acc1a = acc1b = 0;
            curc = c;
        }
        const int2* ge = g_pent + off + half;
        ull tlo = 0, thi = 0;
        for (int st = 0; st < cnt; st += 2) {
            int2 e = ge[st];
            int ao = e.x & 0xFFFF, bo = e.x >> 16;
            ull cgcg = bcast2(__int_as_float(e.y));
            ulonglong2 va = *(const ulonglong2*)(sab + ao);
            ulonglong2 vb = *(const ulonglong2*)(sbb + bo);
            pfma2(tlo, pmul2(cgcg, va.x), vb.x);
            pfma2(thi, pmul2(cgcg, va.y), vb.y);
        }
        ulonglong2 W00 = *(const ulonglong2*)(wp + p * 256 + 4 * q);
        if (s == 0) {
            acc0a = pfma3(W00.x, tlo, acc0a);
            acc0b = pfma3(W00.y, thi, acc0b);
        } else {
            acc1a = pfma3(W00.x, tlo, acc1a);
            acc1b = pfma3(W00.y, thi, acc1b);
        }
    }
    if (curc >= 0) {
        float2 e0 = up2(acc0a), e1 = up2(acc0b), o0 = up2(acc1a), o1 = up2(acc1b);
        e0.x += __shfl_down_sync(0xffffffffu, e0.x, 16);
        e0.y += __shfl_down_sync(0xffffffffu, e0.y, 16);
        e1.x += __shfl_down_sync(0xffffffffu, e1.x, 16);
        e1.y += __shfl_down_sync(0xffffffffu, e1.y, 16);
        o0.x += __shfl_down_sync(0xffffffffu, o0.x, 16);
        o0.y += __shfl_down_sync(0xffffffffu, o0.y, 16);
        o1.x += __shfl_down_sync(0xffffffffu, o1.x, 16);
        o1.y += __shfl_down_sync(0xffffffffu, o1.y, 16);
        if (half == 0) {
            *(float4*)&yo[curc * 64 + 4 * q] = make_float4(e0.x, e0.y, e1.x, e1.y);
            *(float4*)&yo[(NLM + curc) * 64 + 4 * q] = make_float4(o0.x, o0.y, o1.x, o1.y);
        }
    }
}

// ---- TP layer 1: chunked dense (parity-major sa/sb), dual-half 4-feat packed product ----
__global__ void __launch_bounds__(128) k_tp1(const float* __restrict__ W1,
                                             const float* __restrict__ W2,
                                             const float* __restrict__ wp) {
    __shared__ __align__(16) float sa[NLM * 128];   // [a][p*64 + f]  (parity-major, 512B rows)
    __shared__ __align__(16) float sb[NLM * 128];
    int n = blockIdx.x;
    int tid = threadIdx.x;
    int g = tid & 63;
    int drole = tid >> 6;

    const float* yin = g_y1 + (size_t)n * (2 * NLM * 64);
    const float* Wm = drole ? W2 : W1;
    float* dst = drole ? sb : sa;

    for (int p = 0; p < 2; p++) {
#pragma unroll
        for (int d = 0; d < 5; d++) {
            const int nlm = 2 * d + 1, lm0 = d * d;
            float accA[9], accB[9];
#pragma unroll
            for (int i = 0; i < nlm; i++) { accA[i] = 0.f; accB[i] = 0.f; }
#pragma unroll
            for (int kk = 0; kk < 4; kk++) {
                float w[16];
                const float* Wb = Wm + ((p * 5 + d) * 64 + kk * 16) * 64 + g;
#pragma unroll
                for (int f = 0; f < 16; f++) w[f] = Wb[f * 64];
#pragma unroll
                for (int i = 0; i < nlm; i++) {
                    const float4* s4 = (const float4*)(yin + (p * NLM + lm0 + i) * 64 + kk * 16);
#pragma unroll
                    for (int k2 = 0; k2 < 4; k2++) {
                        float4 v = s4[k2];
                        accA[i] = fmaf(v.x, w[4*k2+0], accA[i]);
                        accB[i] = fmaf(v.y, w[4*k2+1], accB[i]);
                        accA[i] = fmaf(v.z, w[4*k2+2], accA[i]);
                        accB[i] = fmaf(v.w, w[4*k2+3], accB[i]);
                    }
                }
            }
#pragma unroll
            for (int i = 0; i < nlm; i++)
                dst[(lm0 + i) * 128 + p * 64 + g] = accA[i] + accB[i];
        }
    }
    __syncthreads();

    int q = tid & 15;
    int half = (tid >> 4) & 1;
    int role = tid >> 5;
    const char* sab = (const char*)sa + 16 * q;
    const char* sbb = (const char*)sb + 16 * q;
    float* yo = g_y2 + (size_t)n * (2 * NLM * 64);
    int nseg = g_rsegcnt[role];
    const int2* rs = g_rseg + role * RSEG_STRIDE;
    ull acc0a = 0, acc0b = 0, acc1a = 0, acc1b = 0;
    int curc = -1;
    for (int si = 0; si < nseg; si++) {
        int2 m = rs[si];
        int off = m.x & 0xFFFFF;
        int cnt = ((unsigned)m.x) >> 20;
        int c = m.y & 31, s = (m.y >> 5) & 1, p = m.y >> 6;
        if (c != curc) {
            if (curc >= 0) {
                float2 e0 = up2(acc0a), e1 = up2(acc0b), o0 = up2(acc1a), o1 = up2(acc1b);
                e0.x += __shfl_down_sync(0xffffffffu, e0.x, 16);
                e0.y += __shfl_down_sync(0xffffffffu, e0.y, 16);
                e1.x += __shfl_down_sync(0xffffffffu, e1.x, 16);
                e1.y += __shfl_down_sync(0xffffffffu, e1.y, 16);
                o0.x += __shfl_down_sync(0xffffffffu, o0.x, 16);
                o0.y += __shfl_down_sync(0xffffffffu, o0.y, 16);
                o1.x += __shfl_down_sync(0xffffffffu, o1.x, 16);
                o1.y += __shfl_down_sync(0xffffffffu, o1.y, 16);
                if (half == 0) {
                    *(float4*)&yo[curc * 64 + 4 * q] = make_float4(e0.x, e0.y, e1.x, e1.y);
                    *(float4*)&yo[(NLM + curc) * 64 + 4 * q] = make_float4(o0.x, o0.y, o1.x, o1.y);
                }
            }
            acc0a = acc0b = acc1a = acc1b = 0;
            curc = c;
        }
        const int2* ge = g_pent2 + off + half;
        ull t00a = 0, t00b = 0, t01a = 0, t01b = 0;
        ull t10a = 0, t10b = 0, t11a = 0, t11b = 0;
        for (int st = 0; st < cnt; st += 2) {
            int2 e = ge[st];
            int ao = e.x & 0xFFFF, bo = e.x >> 16;
            ull cgcg = bcast2(__int_as_float(e.y));
            ulonglong2 a0 = *(const ulonglong2*)(sab + ao);
            ulonglong2 a1 = *(const ulonglong2*)(sab + ao + 256);
            ulonglong2 b0 = *(const ulonglong2*)(sbb + bo);
            ulonglong2 b1 = *(const ulonglong2*)(sbb + bo + 256);
            ull c0a = pmul2(cgcg, a0.x), c0b = pmul2(cgcg, a0.y);
            ull c1a = pmul2(cgcg, a1.x), c1b = pmul2(cgcg, a1.y);
            pfma2(t00a, c0a, b0.x); pfma2(t00b, c0b, b0.y);
            pfma2(t01a, c0a, b1.x); pfma2(t01b, c0b, b1.y);
            pfma2(t10a, c1a, b0.x); pfma2(t10b, c1b, b0.y);
            pfma2(t11a, c1a, b1.x); pfma2(t11b, c1b, b1.y);
        }
        const float* wpb = wp + p * 256 + 4 * q;
        ulonglong2 W00 = *(const ulonglong2*)(wpb);
        ulonglong2 W01 = *(const ulonglong2*)(wpb + 64);
        ulonglong2 W10 = *(const ulonglong2*)(wpb + 128);
        ulonglong2 W11 = *(const ulonglong2*)(wpb + 192);
        ull eva = pfma3(W11.x, t11a, pmul2(W00.x, t00a));
        ull evb = pfma3(W11.y, t11b, pmul2(W00.y, t00b));
        ull oda = pfma3(W10.x, t10a, pmul2(W01.x, t01a));
        ull odb = pfma3(W10.y, t10b, pmul2(W01.y, t01b));
        if (s == 0) {
            acc0a = padd2(acc0a, eva); acc0b = padd2(acc0b, evb);
            acc1a = padd2(acc1a, oda); acc1b = padd2(acc1b, odb);
        } else {
            acc1a = padd2(acc1a, eva); acc1b = padd2(acc1b, evb);
            acc0a = padd2(acc0a, oda); acc0b = padd2(acc0b, odb);
        }
    }
    if (curc >= 0) {
        float2 e0 = up2(acc0a), e1 = up2(acc0b), o0 = up2(acc1a), o1 = up2(acc1b);
        e0.x += __shfl_down_sync(0xffffffffu, e0.x, 16);
        e0.y += __shfl_down_sync(0xffffffffu, e0.y, 16);
        e1.x += __shfl_down_sync(0xffffffffu, e1.x, 16);
        e1.y += __shfl_down_sync(0xffffffffu, e1.y, 16);
        o0.x += __shfl_down_sync(0xffffffffu, o0.x, 16);
        o0.y += __shfl_down_sync(0xffffffffu, o0.y, 16);
        o1.x += __shfl_down_sync(0xffffffffu, o1.x, 16);
        o1.y += __shfl_down_sync(0xffffffffu, o1.y, 16);
        if (half == 0) {
            *(float4*)&yo[curc * 64 + 4 * q] = make_float4(e0.x, e0.y, e1.x, e1.y);
            *(float4*)&yo[(NLM + curc) * 64 + 4 * q] = make_float4(o0.x, o0.y, o1.x, o1.y);
        }
    }
}

// ---- final: te = emb@W_et + b_et; scale, concat, mish ----
__global__ void __launch_bounds__(160) k_final(const int* __restrict__ Z,
                                               const float* __restrict__ emb,
                                               const float* __restrict__ W_et,
                                               const float* __restrict__ b_et,
                                               const float* __restrict__ wf,
                                               float* __restrict__ outp) {
    __shared__ float s_emb[64];
    int n = blockIdx.x;
    int t = threadIdx.x;
    if (t < 64) s_emb[t] = emb[Z[n] * 64 + t];
    __syncthreads();
    if (t >= 144) return;

    float te = b_et[t];
#pragma unroll
    for (int d = 0; d < 64; d++) te = fmaf(s_emb[d], W_et[d * 144 + t], te);

    for (int p = 0; p < 2; p++) {
        for (int lm = 0; lm < NLM; lm++) {
            float yc;
            if (t < 16)
                yc = (p == 0) ? g_y0[(size_t)n * (NLM * 16) + lm * 16 + t] : 0.0f;
            else if (t < 80)
                yc = g_y1[((size_t)n * 2 + p) * (NLM * 64) + lm * 64 + (t - 16)];
            else
                yc = g_y2[((size_t)n * 2 + p) * (NLM * 64) + lm * 64 + (t - 80)];
            float v = te * yc * wf[(p * 5 + c_deg[lm]) * 144 + t];
            if (p == 0 && lm == 0) v += te;
            float e = expf(fminf(v, 40.0f));
            float u = 1.0f + e;
            float u2 = u * u;
            float o = v * (2.0f * u2) / (u2 + 1.0f);
            outp[(((size_t)n * 2 + p) * NLM + lm) * 144 + t] = o;
        }
    }
}

// ---------------- launch ----------------
extern "C" void kernel_launch(void* const* d_in, const int* in_sizes, int n_in,
                              void* d_out, int out_size) {
    const int*   Z    = (const int*)d_in[0];
    const int*   nbr  = (const int*)d_in[1];
    const float* disp = (const float*)d_in[2];
    const float* Wsp  = (const float*)d_in[3];
    const float* emb  = (const float*)d_in[4];
    const float* W_et = (const float*)d_in[5];
    const float* b_et = (const float*)d_in[6];
    const float* norm = (const float*)d_in[7];
    const float* t0W1 = (const float*)d_in[8];
    const float* t0W2 = (const float*)d_in[9];
    const float* t0wp = (const float*)d_in[10];
    const float* t1W1 = (const float*)d_in[11];
    const float* t1W2 = (const float*)d_in[12];
    const float* t1wp = (const float*)d_in[13];
    const float* wfus = (const float*)d_in[14];
    float* outp = (float*)d_out;

    int N = in_sizes[0];
    int E = in_sizes[1] / 2;

    int tot4 = (N * NLM * 16) / 4;
    int zb = (tot4 + 255) / 256;
    k_init_T<<<TBLOCKS + zb, 256>>>(tot4);                              // 1
    k_init_ents_sched<<<1, 1024>>>();                                   // 2
    k_edge<<<(E * 16 + 255) / 256, 256>>>(nbr, disp, Z, Wsp, norm, E);  // 3
    k_tp0<<<N, 128>>>(t0W1, t0W2, t0wp);                                // 4  <- profiled slot
    k_tp1<<<N, 128>>>(t1W1, t1W2, t1wp);                                // 5
    k_final<<<N, 160>>>(Z, emb, W_et, b_et, wfus, outp);                // 6
}

// round 11
// speedup vs baseline: 1.2977x; 1.2977x over previous
#include <cuda_runtime.h>
#include <math.h>

#define NLM 25
#define NPATH 65
#define PI_F 3.14159265358979323846f
#define CUTOFF_F 5.0f
#define MAXN 10240

typedef unsigned long long ull;

// ---------------- scratch ----------------
__device__ float g_y0[MAXN * NLM * 16];
__device__ float g_y1[MAXN * 2 * NLM * 64];
__device__ float g_y2[MAXN * 2 * NLM * 64];

__constant__ int c_deg[NLM] = {0,1,1,1,2,2,2,2,2,3,3,3,3,3,3,3,4,4,4,4,4,4,4,4,4};

// ---------------- packed f32x2 helpers ----------------
__device__ __forceinline__ ull pmul2(ull a, ull b) {
    ull d; asm("mul.rn.f32x2 %0, %1, %2;" : "=l"(d) : "l"(a), "l"(b)); return d;
}
__device__ __forceinline__ void pfma2(ull& t, ull a, ull b) {
    asm("fma.rn.f32x2 %0, %1, %2, %0;" : "+l"(t) : "l"(a), "l"(b));
}
__device__ __forceinline__ ull pfma3(ull a, ull b, ull c) {
    ull d; asm("fma.rn.f32x2 %0, %1, %2, %3;" : "=l"(d) : "l"(a), "l"(b), "l"(c)); return d;
}
__device__ __forceinline__ ull padd2(ull a, ull b) {
    ull d; asm("add.rn.f32x2 %0, %1, %2;" : "=l"(d) : "l"(a), "l"(b)); return d;
}
__device__ __forceinline__ ull bcast2(float v) {
    ull d; asm("mov.b64 %0, {%1, %1};" : "=l"(d) : "f"(v)); return d;
}
__device__ __forceinline__ float2 up2(ull v) {
    float2 r; asm("mov.b64 {%0, %1}, %2;" : "=f"(r.x), "=f"(r.y) : "l"(v)); return r;
}

// ================= compile-time CG construction =================
constexpr double CFACT[16] = {1.0,1.0,2.0,6.0,24.0,120.0,720.0,5040.0,40320.0,
                              362880.0,3628800.0,39916800.0,479001600.0,
                              6227020800.0,87178291200.0,1307674368000.0};

constexpr double csqrt_ct(double x) {
    if (x <= 0.0) return 0.0;
    double g = 1.0, t = x;
    while (t > 4.0) { t *= 0.25; g *= 2.0; }
    while (t < 0.25) { t *= 4.0; g *= 0.5; }
    double y = g * (0.5 + 0.5 * t);   // seed within ~2x
    for (int i = 0; i < 10; i++) y = 0.5 * (y + x / y);
    return y;
}

constexpr int cdeg_ct(int i) { return i < 1 ? 0 : i < 4 ? 1 : i < 9 ? 2 : i < 16 ? 3 : 4; }

constexpr double cg_complex_ct(int l1,int m1,int l2,int m2,int l3,int m3) {
    if (m1 + m2 != m3) return 0.0;
    int lo = l1 > l2 ? l1 - l2 : l2 - l1;
    if (l3 < lo || l3 > l1 + l2) return 0.0;
    double P = CFACT[l1+l2-l3] * CFACT[l1-l2+l3] * CFACT[-l1+l2+l3] / CFACT[l1+l2+l3+1]
             * CFACT[l1+m1] * CFACT[l1-m1] * CFACT[l2+m2] * CFACT[l2-m2]
             * CFACT[l3+m3] * CFACT[l3-m3];
    double sp = csqrt_ct(P);
    int kmin = 0;
    if (l2 - l3 - m1 > kmin) kmin = l2 - l3 - m1;
    if (l1 - l3 + m2 > kmin) kmin = l1 - l3 + m2;
    int kmax = l1 + l2 - l3;
    if (l1 - m1 < kmax) kmax = l1 - m1;
    if (l2 + m2 < kmax) kmax = l2 + m2;
    double s = 0.0;
    for (int k = kmin; k <= kmax; k++) {
        double D = CFACT[k] * CFACT[l1+l2-l3-k] * CFACT[l1-m1-k] * CFACT[l2+m2-k]
                 * CFACT[l3-l2+m1+k] * CFACT[l3-l1-m2+k];
        s += ((k & 1) ? -1.0 : 1.0) * sp / D;
    }
    return csqrt_ct(2.0 * l3 + 1.0) * s;
}

struct DArr { double v[NLM * NLM * NLM]; };
constexpr DArr build_cc() {
    DArr A{};
    for (int l1 = 0; l1 <= 4; l1++)
    for (int m1 = -l1; m1 <= l1; m1++)
    for (int l2 = 0; l2 <= 4; l2++)
    for (int m2 = -l2; m2 <= l2; m2++) {
        int lo = l1 > l2 ? l1 - l2 : l2 - l1;
        int hi = (l1 + l2 > 4) ? 4 : (l1 + l2);
        for (int l3 = lo; l3 <= hi; l3++) {
            int m3 = m1 + m2;
            if (m3 >= -l3 && m3 <= l3)
                A.v[((l1*l1+l1+m1)*NLM + (l2*l2+l2+m2))*NLM + (l3*l3+l3+m3)]
                    = cg_complex_ct(l1, m1, l2, m2, l3, m3);
        }
    }
    return A;
}
constexpr DArr CC = build_cc();

struct URct { int col[2]; double re[2], im[2]; int n; };
constexpr URct u_row_ct(int l, int m) {
    URct u{};
    int off = l * l + l;
    const double is2 = 0.7071067811865476;
    if (m == 0) { u.col[0] = off; u.re[0] = 1.0; u.im[0] = 0.0; u.n = 1; return u; }
    if (m > 0) {
        double sgn = (m & 1) ? -1.0 : 1.0;
        u.col[0] = off + m; u.re[0] = sgn * is2; u.im[0] = 0.0;
        u.col[1] = off - m; u.re[1] = is2;       u.im[1] = 0.0;
        u.n = 2; return u;
    }
    int mm = -m;
    double sgn = (mm & 1) ? -1.0 : 1.0;
    u.col[0] = off - mm; u.re[0] = 0.0; u.im[0] = is2;
    u.col[1] = off + mm; u.re[1] = 0.0; u.im[1] = -sgn * is2;
    u.n = 2;
    return u;
}

constexpr float realCG(int i, int j, int k) {
    int li = cdeg_ct(i), mi = i - li*li - li;
    int lj = cdeg_ct(j), mj = j - lj*lj - lj;
    int lk = cdeg_ct(k), mk = k - lk*lk - lk;
    URct ua = u_row_ct(li, mi), ub = u_row_ct(lj, mj), uc = u_row_ct(lk, mk);
    double tre = 0.0, tim = 0.0;
    for (int aa = 0; aa < ua.n; aa++)
      for (int bb = 0; bb < ub.n; bb++) {
        double wre = ua.re[aa]*ub.re[bb] - ua.im[aa]*ub.im[bb];
        double wim = ua.re[aa]*ub.im[bb] + ua.im[aa]*ub.re[bb];
        for (int ci = 0; ci < uc.n; ci++) {
            double cv = CC.v[(ua.col[aa]*NLM + ub.col[bb])*NLM + uc.col[ci]];
            if (cv == 0.0) continue;
            double ur3 = uc.re[ci], ui3 = -uc.im[ci];
            tre += (wre*ur3 - wim*ui3) * cv;
            tim += (wre*ui3 + wim*ur3) * cv;
        }
      }
    double v = tre + tim;
    if (v < 1e-12 && v > -1e-12) return 0.0f;
    return (float)v;
}

// ---- compile-time schedule: 4 roles own disjoint c's; segments grouped by c then path;
//      entries grouped into a-runs ----
constexpr int SEG_MAX = 256, RUN_MAX = 1024, ENT_MAX = 2048;
struct RoleTab {
    int nseg, nrun, nent;
    int seg_c[SEG_MAX]; int seg_s[SEG_MAX]; int seg_path[SEG_MAX];
    int seg_run_off[SEG_MAX + 1];
    int run_a[RUN_MAX];
    int run_ent_off[RUN_MAX + 1];
    int ent_b[ENT_MAX];
    float ent_cg[ENT_MAX];
};
struct Tab { RoleTab r[4]; };

constexpr Tab build_tab() {
    Tab T{};
    int pl1[NPATH]{}, pl2[NPATH]{}, pl3[NPATH]{};
    int np = 0;
    for (int l1 = 0; l1 <= 4; l1++)
      for (int l2 = 0; l2 <= 4; l2++) {
        int lo = l1 > l2 ? l1 - l2 : l2 - l1;
        int hi = (l1 + l2 > 4) ? 4 : (l1 + l2);
        for (int l3 = lo; l3 <= hi; l3++) { pl1[np]=l1; pl2[np]=l2; pl3[np]=l3; np++; }
      }
    // approximate per-c weight (exact partition not needed for correctness)
    int wsum[NLM]{};
    for (int p = 0; p < np; p++) {
        int l1 = pl1[p], l2 = pl2[p], l3 = pl3[p];
        int est = ((2*l1+1)*(2*l2+1) + 1) / 2 + 8;
        for (int c = l3*l3; c < (l3+1)*(l3+1); c++) wsum[c] += est;
    }
    int csel[NLM]{}; bool used[NLM]{}; int load[4]{};
    for (int it = 0; it < NLM; it++) {
        int best = -1, bw = -1;
        for (int c = 0; c < NLM; c++)
            if (!used[c] && wsum[c] > bw) { bw = wsum[c]; best = c; }
        int km = 0;
        for (int k2 = 1; k2 < 4; k2++) if (load[k2] < load[km]) km = k2;
        csel[best] = km; load[km] += bw; used[best] = true;
    }
    for (int r = 0; r < 4; r++) {
        RoleTab& R = T.r[r];
        R.seg_run_off[0] = 0; R.run_ent_off[0] = 0;
        for (int c = 0; c < NLM; c++) {
            if (csel[c] != r) continue;
            int l3c = cdeg_ct(c);
            for (int p = 0; p < np; p++) {
                if (pl3[p] != l3c) continue;
                int l1 = pl1[p], l2 = pl2[p];
                int srun = R.nrun;
                for (int a = l1*l1; a < (l1+1)*(l1+1); a++) {
                    int estart = R.nent;
                    for (int b = l2*l2; b < (l2+1)*(l2+1); b++) {
                        float v = realCG(a, b, c);
                        if (v != 0.0f) { R.ent_b[R.nent] = b; R.ent_cg[R.nent] = v; R.nent++; }
                    }
                    if (R.nent > estart) {
                        R.run_a[R.nrun] = a; R.nrun++; R.run_ent_off[R.nrun] = R.nent;
                    }
                }
                if (R.nrun > srun) {
                    R.seg_c[R.nseg] = c;
                    R.seg_s[R.nseg] = (l1 + l2 + l3c) & 1;
                    R.seg_path[R.nseg] = p;
                    R.nseg++; R.seg_run_off[R.nseg] = R.nrun;
                }
            }
        }
    }
    return T;
}
constexpr Tab TAB = build_tab();

// ================= template-generated TP products =================
// --- tp0 (single-parity rows, 256B stride) ---
template<int R, int E, int EEND> struct Ent0T {
    static __device__ __forceinline__ void go(ull va, const char* sbb, ull& t) {
        constexpr int boff = TAB.r[R].ent_b[E] * 256;
        constexpr float cgf = TAB.r[R].ent_cg[E];
        ull vb = *(const ull*)(sbb + boff);
        pfma2(t, pmul2(bcast2(cgf), va), vb);
        Ent0T<R, E + 1, EEND>::go(va, sbb, t);
    }
};
template<int R, int E> struct Ent0T<R, E, E> {
    static __device__ __forceinline__ void go(ull, const char*, ull&) {}
};

template<int R, int RI, int REND> struct Run0T {
    static __device__ __forceinline__ void go(const char* sab, const char* sbb, ull& t) {
        constexpr int aoff = TAB.r[R].run_a[RI] * 256;
        constexpr int e0 = TAB.r[R].run_ent_off[RI];
        constexpr int e1 = TAB.r[R].run_ent_off[RI + 1];
        ull va = *(const ull*)(sab + aoff);
        Ent0T<R, e0, e1>::go(va, sbb, t);
        Run0T<R, RI + 1, REND>::go(sab, sbb, t);
    }
};
template<int R, int RI> struct Run0T<R, RI, RI> {
    static __device__ __forceinline__ void go(const char*, const char*, ull&) {}
};

template<int R, int SI, int SEND> struct Seg0T {
    static __device__ __forceinline__ void go(const char* sab, const char* sbb,
            const float* wq, float* yo, ull& acc0, ull& acc1) {
        constexpr int c = TAB.r[R].seg_c[SI];
        constexpr int s = TAB.r[R].seg_s[SI];
        constexpr int p = TAB.r[R].seg_path[SI];
        constexpr int r0 = TAB.r[R].seg_run_off[SI];
        constexpr int r1 = TAB.r[R].seg_run_off[SI + 1];
        ull t = 0;
        Run0T<R, r0, r1>::go(sab, sbb, t);
        ull W00 = *(const ull*)(wq + p * 256);
        if (s == 0) acc0 = pfma3(W00, t, acc0);
        else        acc1 = pfma3(W00, t, acc1);
        constexpr bool flush = (SI + 1 == SEND) || (TAB.r[R].seg_c[SI + 1] != c);
        if (flush) {
            *(float2*)(yo + c * 64) = up2(acc0);
            *(float2*)(yo + (NLM + c) * 64) = up2(acc1);
            acc0 = 0; acc1 = 0;
        }
        Seg0T<R, SI + 1, SEND>::go(sab, sbb, wq, yo, acc0, acc1);
    }
};
template<int R, int SI> struct Seg0T<R, SI, SI> {
    static __device__ __forceinline__ void go(const char*, const char*,
            const float*, float*, ull&, ull&) {}
};

// --- tp1 (2-parity rows, parity-major 512B stride) ---
template<int R, int E, int EEND> struct Ent1T {
    static __device__ __forceinline__ void go(ull a0, ull a1, const char* sbb,
            ull& t00, ull& t01, ull& t10, ull& t11) {
        constexpr int boff = TAB.r[R].ent_b[E] * 512;
        constexpr float cgf = TAB.r[R].ent_cg[E];
        ull cgcg = bcast2(cgf);
        ull b0 = *(const ull*)(sbb + boff);
        ull b1 = *(const ull*)(sbb + boff + 256);
        ull c0 = pmul2(cgcg, a0), c1 = pmul2(cgcg, a1);
        pfma2(t00, c0, b0); pfma2(t01, c0, b1);
        pfma2(t10, c1, b0); pfma2(t11, c1, b1);
        Ent1T<R, E + 1, EEND>::go(a0, a1, sbb, t00, t01, t10, t11);
    }
};
template<int R, int E> struct Ent1T<R, E, E> {
    static __device__ __forceinline__ void go(ull, ull, const char*, ull&, ull&, ull&, ull&) {}
};

template<int R, int RI, int REND> struct Run1T {
    static __device__ __forceinline__ void go(const char* sab, const char* sbb,
            ull& t00, ull& t01, ull& t10, ull& t11) {
        constexpr int aoff = TAB.r[R].run_a[RI] * 512;
        constexpr int e0 = TAB.r[R].run_ent_off[RI];
        constexpr int e1 = TAB.r[R].run_ent_off[RI + 1];
        ull a0 = *(const ull*)(sab + aoff);
        ull a1 = *(const ull*)(sab + aoff + 256);
        Ent1T<R, e0, e1>::go(a0, a1, sbb, t00, t01, t10, t11);
        Run1T<R, RI + 1, REND>::go(sab, sbb, t00, t01, t10, t11);
    }
};
template<int R, int RI> struct Run1T<R, RI, RI> {
    static __device__ __forceinline__ void go(const char*, const char*, ull&, ull&, ull&, ull&) {}
};

template<int R, int SI, int SEND> struct Seg1T {
    static __device__ __forceinline__ void go(const char* sab, const char* sbb,
            const float* wq, float* yo, ull& acc0, ull& acc1) {
        constexpr int c = TAB.r[R].seg_c[SI];
        constexpr int s = TAB.r[R].seg_s[SI];
        constexpr int p = TAB.r[R].seg_path[SI];
        constexpr int r0 = TAB.r[R].seg_run_off[SI];
        constexpr int r1 = TAB.r[R].seg_run_off[SI + 1];
        ull t00 = 0, t01 = 0, t10 = 0, t11 = 0;
        Run1T<R, r0, r1>::go(sab, sbb, t00, t01, t10, t11);
        const float* wpb = wq + p * 256;
        ull W00 = *(const ull*)(wpb);
        ull W01 = *(const ull*)(wpb + 64);
        ull W10 = *(const ull*)(wpb + 128);
        ull W11 = *(const ull*)(wpb + 192);
        ull ev = pfma3(W11, t11, pmul2(W00, t00));
        ull od = pfma3(W10, t10, pmul2(W01, t01));
        if (s == 0) { acc0 = padd2(acc0, ev); acc1 = padd2(acc1, od); }
        else        { acc1 = padd2(acc1, ev); acc0 = padd2(acc0, od); }
        constexpr bool flush = (SI + 1 == SEND) || (TAB.r[R].seg_c[SI + 1] != c);
        if (flush) {
            *(float2*)(yo + c * 64) = up2(acc0);
            *(float2*)(yo + (NLM + c) * 64) = up2(acc1);
            acc0 = 0; acc1 = 0;
        }
        Seg1T<R, SI + 1, SEND>::go(sab, sbb, wq, yo, acc0, acc1);
    }
};
template<int R, int SI> struct Seg1T<R, SI, SI> {
    static __device__ __forceinline__ void go(const char*, const char*,
            const float*, float*, ull&, ull&) {}
};

// ================= stage kernels =================
__global__ void k_zero(int total4) {
    int t = blockIdx.x * blockDim.x + threadIdx.x;
    if (t < total4) ((float4*)g_y0)[t] = make_float4(0.f, 0.f, 0.f, 0.f);
}

__global__ void k_edge(const int* __restrict__ nbr, const float* __restrict__ disp,
                       const int* __restrict__ Z, const float* __restrict__ Wsp,
                       const float* __restrict__ normp, int E) {
    int t = blockIdx.x * blockDim.x + threadIdx.x;
    int e = t >> 4, lane = t & 15;
    bool valid = (e < E);
    int i = 0, j = 0;
    float dx = 0.f, dy = 0.f, dz = 1.f;
    if (valid) {
        i = nbr[2 * e]; j = nbr[2 * e + 1];
        dx = disp[3 * e]; dy = disp[3 * e + 1]; dz = disp[3 * e + 2];
    }
    float r = sqrtf(dx * dx + dy * dy + dz * dz + 1e-12f);
    float inv = 1.0f / r;
    float x = dx * inv, y = dy * inv, z = dz * inv;
    bool ok = valid && (r < CUTOFF_F);
    float fcut = 0.5f * (cosf(PI_F * fminf(r * (1.0f / CUTOFF_F), 1.0f)) + 1.0f);

    int Zj = valid ? Z[j] : 0;
    const float gamma = 10.24f;
    float d = r - (float)lane * (CUTOFF_F / 15.0f);
    float rbf = expf(-gamma * d * d);

    const float* W = Wsp + Zj * 256 + lane;
    float gsum = 0.0f;
#pragma unroll
    for (int k = 0; k < 16; k++) {
        float rb = __shfl_sync(0xffffffffu, rbf, k, 16);
        gsum = fmaf(rb, W[k * 16], gsum);
    }
    if (!ok) return;
    float g = gsum * fcut / normp[0];

    float x2 = x * x, y2 = y * y, z2 = z * z;
    float Y[NLM];
    Y[0]  = 0.5f * sqrtf(1.0f / PI_F);
    Y[1]  = sqrtf(3.0f / (4.0f * PI_F)) * y;
    Y[2]  = sqrtf(3.0f / (4.0f * PI_F)) * z;
    Y[3]  = sqrtf(3.0f / (4.0f * PI_F)) * x;
    Y[4]  = 0.5f * sqrtf(15.0f / PI_F) * x * y;
    Y[5]  = 0.5f * sqrtf(15.0f / PI_F) * y * z;
    Y[6]  = 0.25f * sqrtf(5.0f / PI_F) * (3.0f * z2 - 1.0f);
    Y[7]  = 0.5f * sqrtf(15.0f / PI_F) * x * z;
    Y[8]  = 0.25f * sqrtf(15.0f / PI_F) * (x2 - y2);
    Y[9]  = 0.25f * sqrtf(35.0f / (2.0f * PI_F)) * y * (3.0f * x2 - y2);
    Y[10] = 0.5f * sqrtf(105.0f / PI_F) * x * y * z;
    Y[11] = 0.25f * sqrtf(21.0f / (2.0f * PI_F)) * y * (5.0f * z2 - 1.0f);
    Y[12] = 0.25f * sqrtf(7.0f / PI_F) * z * (5.0f * z2 - 3.0f);
    Y[13] = 0.25f * sqrtf(21.0f / (2.0f * PI_F)) * x * (5.0f * z2 - 1.0f);
    Y[14] = 0.25f * sqrtf(105.0f / PI_F) * z * (x2 - y2);
    Y[15] = 0.25f * sqrtf(35.0f / (2.0f * PI_F)) * x * (x2 - 3.0f * y2);
    Y[16] = 0.75f * sqrtf(35.0f / PI_F) * x * y * (x2 - y2);
    Y[17] = 0.75f * sqrtf(35.0f / (2.0f * PI_F)) * y * z * (3.0f * x2 - y2);
    Y[18] = 0.75f * sqrtf(5.0f / PI_F) * x * y * (7.0f * z2 - 1.0f);
    Y[19] = 0.75f * sqrtf(5.0f / (2.0f * PI_F)) * y * z * (7.0f * z2 - 3.0f);
    Y[20] = (3.0f / 16.0f) * sqrtf(1.0f / PI_F) * (35.0f * z2 * z2 - 30.0f * z2 + 3.0f);
    Y[21] = 0.75f * sqrtf(5.0f / (2.0f * PI_F)) * x * z * (7.0f * z2 - 3.0f);
    Y[22] = (3.0f / 8.0f) * sqrtf(5.0f / PI_F) * (x2 - y2) * (7.0f * z2 - 1.0f);
    Y[23] = 0.75f * sqrtf(35.0f / (2.0f * PI_F)) * x * z * (x2 - 3.0f * y2);
    Y[24] = (3.0f / 16.0f) * sqrtf(35.0f / PI_F) * (x2 * x2 - 6.0f * x2 * y2 + y2 * y2);

    float* dst = g_y0 + (size_t)i * (NLM * 16) + lane;
#pragma unroll
    for (int lm = 0; lm < NLM; lm++)
        atomicAdd(dst + lm * 16, Y[lm] * g);
}

// ---- TP layer 0 ----
__global__ void __launch_bounds__(128) k_tp0(const float* __restrict__ W1,
                                             const float* __restrict__ W2,
                                             const float* __restrict__ wp) {
    __shared__ __align__(16) float sa[NLM * 64];
    __shared__ __align__(16) float sb[NLM * 64];
    int n = blockIdx.x;
    int tid = threadIdx.x;
    int g = tid & 63;
    int drole = tid >> 6;

    const float* yin = g_y0 + (size_t)n * (NLM * 16);
    const float* Wm = drole ? W2 : W1;
    float* dst = drole ? sb : sa;

    for (int d = 0; d < 5; d++) {
        float w[16];
        const float* Wb = Wm + (d * 16) * 64 + g;
#pragma unroll
        for (int f = 0; f < 16; f++) w[f] = Wb[f * 64];
        for (int lm = d * d; lm < (d + 1) * (d + 1); lm++) {
            const float4* s4 = (const float4*)(yin + lm * 16);
            float a0 = 0.f, a1 = 0.f, a2 = 0.f, a3 = 0.f;
#pragma unroll
            for (int k = 0; k < 4; k++) {
                float4 v = s4[k];
                a0 = fmaf(v.x, w[4*k+0], a0);
                a1 = fmaf(v.y, w[4*k+1], a1);
                a2 = fmaf(v.z, w[4*k+2], a2);
                a3 = fmaf(v.w, w[4*k+3], a3);
            }
            dst[lm * 64 + g] = (a0 + a1) + (a2 + a3);
        }
    }
    __syncthreads();

    int q = tid & 31;
    int role = tid >> 5;
    const char* sab = (const char*)sa + 8 * q;
    const char* sbb = (const char*)sb + 8 * q;
    const float* wq = wp + 2 * q;
    float* yo = g_y1 + (size_t)n * (2 * NLM * 64) + 2 * q;
    ull acc0 = 0, acc1 = 0;
    if (role == 0)      Seg0T<0, 0, TAB.r[0].nseg>::go(sab, sbb, wq, yo, acc0, acc1);
    else if (role == 1) Seg0T<1, 0, TAB.r[1].nseg>::go(sab, sbb, wq, yo, acc0, acc1);
    else if (role == 2) Seg0T<2, 0, TAB.r[2].nseg>::go(sab, sbb, wq, yo, acc0, acc1);
    else                Seg0T<3, 0, TAB.r[3].nseg>::go(sab, sbb, wq, yo, acc0, acc1);
}

// ---- TP layer 1 ----
__global__ void __launch_bounds__(128) k_tp1(const float* __restrict__ W1,
                                             const float* __restrict__ W2,
                                             const float* __restrict__ wp) {
    __shared__ __align__(16) float sa[NLM * 128];   // [a][p*64 + f] parity-major
    __shared__ __align__(16) float sb[NLM * 128];
    int n = blockIdx.x;
    int tid = threadIdx.x;
    int g = tid & 63;
    int drole = tid >> 6;

    const float* yin = g_y1 + (size_t)n * (2 * NLM * 64);
    const float* Wm = drole ? W2 : W1;
    float* dst = drole ? sb : sa;

    for (int p = 0; p < 2; p++) {
#pragma unroll
        for (int d = 0; d < 5; d++) {
            const int nlm = 2 * d + 1, lm0 = d * d;
            float accA[9], accB[9];
#pragma unroll
            for (int i = 0; i < nlm; i++) { accA[i] = 0.f; accB[i] = 0.f; }
#pragma unroll
            for (int kk = 0; kk < 4; kk++) {
                float w[16];
                const float* Wb = Wm + ((p * 5 + d) * 64 + kk * 16) * 64 + g;
#pragma unroll
                for (int f = 0; f < 16; f++) w[f] = Wb[f * 64];
#pragma unroll
                for (int i = 0; i < nlm; i++) {
                    const float4* s4 = (const float4*)(yin + (p * NLM + lm0 + i) * 64 + kk * 16);
#pragma unroll
                    for (int k2 = 0; k2 < 4; k2++) {
                        float4 v = s4[k2];
                        accA[i] = fmaf(v.x, w[4*k2+0], accA[i]);
                        accB[i] = fmaf(v.y, w[4*k2+1], accB[i]);
                        accA[i] = fmaf(v.z, w[4*k2+2], accA[i]);
                        accB[i] = fmaf(v.w, w[4*k2+3], accB[i]);
                    }
                }
            }
#pragma unroll
            for (int i = 0; i < nlm; i++)
                dst[(lm0 + i) * 128 + p * 64 + g] = accA[i] + accB[i];
        }
    }
    __syncthreads();

    int q = tid & 31;
    int role = tid >> 5;
    const char* sab = (const char*)sa + 8 * q;
    const char* sbb = (const char*)sb + 8 * q;
    const float* wq = wp + 2 * q;
    float* yo = g_y2 + (size_t)n * (2 * NLM * 64) + 2 * q;
    ull acc0 = 0, acc1 = 0;
    if (role == 0)      Seg1T<0, 0, TAB.r[0].nseg>::go(sab, sbb, wq, yo, acc0, acc1);
    else if (role == 1) Seg1T<1, 0, TAB.r[1].nseg>::go(sab, sbb, wq, yo, acc0, acc1);
    else if (role == 2) Seg1T<2, 0, TAB.r[2].nseg>::go(sab, sbb, wq, yo, acc0, acc1);
    else                Seg1T<3, 0, TAB.r[3].nseg>::go(sab, sbb, wq, yo, acc0, acc1);
}

// ---- final ----
__global__ void __launch_bounds__(160) k_final(const int* __restrict__ Z,
                                               const float* __restrict__ emb,
                                               const float* __restrict__ W_et,
                                               const float* __restrict__ b_et,
                                               const float* __restrict__ wf,
                                               float* __restrict__ outp) {
    __shared__ float s_emb[64];
    int n = blockIdx.x;
    int t = threadIdx.x;
    if (t < 64) s_emb[t] = emb[Z[n] * 64 + t];
    __syncthreads();
    if (t >= 144) return;

    float te = b_et[t];
#pragma unroll
    for (int d = 0; d < 64; d++) te = fmaf(s_emb[d], W_et[d * 144 + t], te);

    for (int p = 0; p < 2; p++) {
        for (int lm = 0; lm < NLM; lm++) {
            float yc;
            if (t < 16)
                yc = (p == 0) ? g_y0[(size_t)n * (NLM * 16) + lm * 16 + t] : 0.0f;
            else if (t < 80)
                yc = g_y1[((size_t)n * 2 + p) * (NLM * 64) + lm * 64 + (t - 16)];
            else
                yc = g_y2[((size_t)n * 2 + p) * (NLM * 64) + lm * 64 + (t - 80)];
            float v = te * yc * wf[(p * 5 + c_deg[lm]) * 144 + t];
            if (p == 0 && lm == 0) v += te;
            float e = expf(fminf(v, 40.0f));
            float u = 1.0f + e;
            float u2 = u * u;
            float o = v * (2.0f * u2) / (u2 + 1.0f);
            outp[(((size_t)n * 2 + p) * NLM + lm) * 144 + t] = o;
        }
    }
}

// ---------------- launch ----------------
extern "C" void kernel_launch(void* const* d_in, const int* in_sizes, int n_in,
                              void* d_out, int out_size) {
    const int*   Z    = (const int*)d_in[0];
    const int*   nbr  = (const int*)d_in[1];
    const float* disp = (const float*)d_in[2];
    const float* Wsp  = (const float*)d_in[3];
    const float* emb  = (const float*)d_in[4];
    const float* W_et = (const float*)d_in[5];
    const float* b_et = (const float*)d_in[6];
    const float* norm = (const float*)d_in[7];
    const float* t0W1 = (const float*)d_in[8];
    const float* t0W2 = (const float*)d_in[9];
    const float* t0wp = (const float*)d_in[10];
    const float* t1W1 = (const float*)d_in[11];
    const float* t1W2 = (const float*)d_in[12];
    const float* t1wp = (const float*)d_in[13];
    const float* wfus = (const float*)d_in[14];
    float* outp = (float*)d_out;

    int N = in_sizes[0];
    int E = in_sizes[1] / 2;

    int tot4 = (N * NLM * 16) / 4;
    k_zero<<<(tot4 + 255) / 256, 256>>>(tot4);                          // 1
    k_edge<<<(E * 16 + 255) / 256, 256>>>(nbr, disp, Z, Wsp, norm, E);  // 2
    k_tp0<<<N, 128>>>(t0W1, t0W2, t0wp);                                // 3
    k_tp1<<<N, 128>>>(t1W1, t1W2, t1wp);                                // 4  <- profiled slot
    k_final<<<N, 160>>>(Z, emb, W_et, b_et, wfus, outp);                // 5
}